// round 1
// baseline (speedup 1.0000x reference)
#include <cuda_runtime.h>
#include <cuda_bf16.h>
#include <math.h>

// Problem constants
#define BATCH 2
#define SEQ   2048
#define DIM   2048
#define HEADS 16
#define HD    128           // head dim
#define MROWS (BATCH*SEQ)   // 4096

// ---------------------------------------------------------------------------
// Scratch buffers (device globals; no allocation allowed)
// ---------------------------------------------------------------------------
static __device__ float g_Q[MROWS * DIM];
static __device__ float g_K[MROWS * DIM];
static __device__ float g_V[MROWS * DIM];
static __device__ float g_O[MROWS * DIM];

// ---------------------------------------------------------------------------
// SGEMM with bias: C[M,N] = A[M,K] @ B[K,N] + bias[N]
// BM=BN=128, BK=16, 256 threads, 8x8 per-thread tile
// ---------------------------------------------------------------------------
#define GBM 128
#define GBN 128
#define GBK 16
#define GTM 8
#define GTN 8

__global__ void __launch_bounds__(256)
sgemm_bias_kernel(const float* __restrict__ A, const float* __restrict__ B,
                  const float* __restrict__ bias, float* __restrict__ C,
                  int M, int N, int K)
{
    __shared__ float As[GBK][GBM];   // transposed A tile
    __shared__ float Bs[GBK][GBN];

    const int tid = threadIdx.x;
    const int tx = tid % 16;         // col group
    const int ty = tid / 16;         // row group
    const int rowBase = blockIdx.y * GBM;
    const int colBase = blockIdx.x * GBN;

    float acc[GTM][GTN];
#pragma unroll
    for (int i = 0; i < GTM; i++)
#pragma unroll
        for (int j = 0; j < GTN; j++) acc[i][j] = 0.f;

    // A tile load mapping: each thread loads two float4
    const int aRow = tid / 4;         // 0..63
    const int aCol = (tid % 4) * 4;   // 0,4,8,12
    // B tile load mapping
    const int bRow = tid / 32;        // 0..7
    const int bCol = (tid % 32) * 4;  // 0..124

    for (int k0 = 0; k0 < K; k0 += GBK) {
#pragma unroll
        for (int i = 0; i < 2; i++) {
            int r = aRow + i * 64;
            float4 v = *(const float4*)(A + (size_t)(rowBase + r) * K + k0 + aCol);
            As[aCol + 0][r] = v.x;
            As[aCol + 1][r] = v.y;
            As[aCol + 2][r] = v.z;
            As[aCol + 3][r] = v.w;
        }
#pragma unroll
        for (int i = 0; i < 2; i++) {
            int r = bRow + i * 8;
            float4 v = *(const float4*)(B + (size_t)(k0 + r) * N + colBase + bCol);
            *(float4*)&Bs[r][bCol] = v;
        }
        __syncthreads();

#pragma unroll
        for (int kk = 0; kk < GBK; kk++) {
            float ra[GTM], rb[GTN];
#pragma unroll
            for (int i = 0; i < GTM; i++) ra[i] = As[kk][ty * GTM + i];
#pragma unroll
            for (int j = 0; j < GTN; j++) rb[j] = Bs[kk][tx * GTN + j];
#pragma unroll
            for (int i = 0; i < GTM; i++)
#pragma unroll
                for (int j = 0; j < GTN; j++)
                    acc[i][j] += ra[i] * rb[j];
        }
        __syncthreads();
    }

#pragma unroll
    for (int i = 0; i < GTM; i++) {
        int r = rowBase + ty * GTM + i;
#pragma unroll
        for (int j = 0; j < GTN; j += 4) {
            int c = colBase + tx * GTN + j;
            float4 v;
            v.x = acc[i][j + 0] + bias[c + 0];
            v.y = acc[i][j + 1] + bias[c + 1];
            v.z = acc[i][j + 2] + bias[c + 2];
            v.w = acc[i][j + 3] + bias[c + 3];
            *(float4*)(C + (size_t)r * N + c) = v;
        }
    }
}

// ---------------------------------------------------------------------------
// Flash attention (fp32, causal + ALiBi), 64-query tiles, 64-key tiles
// Q/K/V/O layout: [b*SEQ + t][h*HD + d]   (stride DIM between tokens)
// 256 threads: thread (ty,tx) with ty=tid/16, tx=tid%16
//   S phase: rows ty*4..+3, cols tx*4..+3
//   O phase: rows ty*4..+3, cols tx*8..+7
// ---------------------------------------------------------------------------
#define FQ   64
#define FKV  64
#define QSTR 132   // sQ row stride (pad 4)  -> broadcast reads, float4-aligned
#define KSTR 129   // sK row stride (pad 1)  -> 2-way max conflict on kv reads
#define VSTR 132   // sV row stride
#define PSTR 68    // sP row stride

__global__ void __launch_bounds__(256)
flash_attn_kernel(const float* __restrict__ Q, const float* __restrict__ K,
                  const float* __restrict__ V, const float* __restrict__ slopes,
                  float* __restrict__ O)
{
    extern __shared__ float sm[];
    float* sQ = sm;                       // FQ  * QSTR
    float* sK = sQ + FQ * QSTR;           // FKV * KSTR
    float* sV = sK + FKV * KSTR;           // FKV * VSTR
    float* sP = sV + FKV * VSTR;           // FQ  * PSTR

    const int NT = SEQ / FQ;              // 32
    const int qt = NT - 1 - blockIdx.x;   // heavy tiles first
    const int h  = blockIdx.y;
    const int b  = blockIdx.z;
    const int tid = threadIdx.x;
    const int tx = tid % 16;
    const int ty = tid / 16;

    const float slope = slopes[h];
    const float scale = 0.08838834764831845f;  // 1/sqrt(128)

    const size_t base = (size_t)b * SEQ * DIM + (size_t)h * HD;
    const int qs = qt * FQ;

    // Load Q tile (64 x 128), float4 global loads
    for (int i = tid; i < FQ * (HD / 4); i += 256) {
        int r = i / (HD / 4);
        int c = (i % (HD / 4)) * 4;
        float4 v = *(const float4*)(Q + base + (size_t)(qs + r) * DIM + c);
        *(float4*)&sQ[r * QSTR + c] = v;
    }

    float m[4], l[4], o[4][8];
#pragma unroll
    for (int i = 0; i < 4; i++) {
        m[i] = -1e30f; l[i] = 0.f;
#pragma unroll
        for (int j = 0; j < 8; j++) o[i][j] = 0.f;
    }

    for (int kt = 0; kt <= qt; kt++) {
        const int ks = kt * FKV;
        __syncthreads();   // previous iteration done with sK/sV/sP

        // Load K (scalar stores, stride 129) and V (float4, stride 132)
        for (int i = tid; i < FKV * (HD / 4); i += 256) {
            int r = i / (HD / 4);
            int c = (i % (HD / 4)) * 4;
            float4 kv4 = *(const float4*)(K + base + (size_t)(ks + r) * DIM + c);
            sK[r * KSTR + c + 0] = kv4.x;
            sK[r * KSTR + c + 1] = kv4.y;
            sK[r * KSTR + c + 2] = kv4.z;
            sK[r * KSTR + c + 3] = kv4.w;
            float4 vv4 = *(const float4*)(V + base + (size_t)(ks + r) * DIM + c);
            *(float4*)&sV[r * VSTR + c] = vv4;
        }
        __syncthreads();

        // ---- S = Q K^T (each thread: 4x4) ----
        float s[4][4];
#pragma unroll
        for (int i = 0; i < 4; i++)
#pragma unroll
            for (int j = 0; j < 4; j++) s[i][j] = 0.f;

#pragma unroll 4
        for (int d = 0; d < HD; d++) {
            float qv[4], kv[4];
#pragma unroll
            for (int i = 0; i < 4; i++) qv[i] = sQ[(ty * 4 + i) * QSTR + d];
#pragma unroll
            for (int j = 0; j < 4; j++) kv[j] = sK[(tx * 4 + j) * KSTR + d];
#pragma unroll
            for (int i = 0; i < 4; i++)
#pragma unroll
                for (int j = 0; j < 4; j++)
                    s[i][j] += qv[i] * kv[j];
        }

        // ---- scale + ALiBi + causal mask, row max ----
        float rmax[4];
#pragma unroll
        for (int i = 0; i < 4; i++) {
            const int gi = qs + ty * 4 + i;
            rmax[i] = -1e30f;
#pragma unroll
            for (int j = 0; j < 4; j++) {
                const int gj = ks + tx * 4 + j;
                float val = s[i][j] * scale + slope * (float)(gj - gi);
                if (gj > gi) val = -1e30f;
                s[i][j] = val;
                rmax[i] = fmaxf(rmax[i], val);
            }
        }
        // reduce max across the 16 tx lanes (they are a contiguous 16-lane group)
#pragma unroll
        for (int off = 1; off < 16; off <<= 1)
#pragma unroll
            for (int i = 0; i < 4; i++)
                rmax[i] = fmaxf(rmax[i], __shfl_xor_sync(0xffffffff, rmax[i], off));

        // ---- online softmax update ----
#pragma unroll
        for (int i = 0; i < 4; i++) {
            float mnew = fmaxf(m[i], rmax[i]);
            float corr = __expf(m[i] - mnew);
            m[i] = mnew;
            l[i] *= corr;
#pragma unroll
            for (int j = 0; j < 8; j++) o[i][j] *= corr;
            float sum = 0.f;
#pragma unroll
            for (int j = 0; j < 4; j++) {
                float p = __expf(s[i][j] - mnew);
                s[i][j] = p;
                sum += p;
            }
#pragma unroll
            for (int off = 1; off < 16; off <<= 1)
                sum += __shfl_xor_sync(0xffffffff, sum, off);
            l[i] += sum;
        }

        // store P to shared
#pragma unroll
        for (int i = 0; i < 4; i++)
#pragma unroll
            for (int j = 0; j < 4; j++)
                sP[(ty * 4 + i) * PSTR + tx * 4 + j] = s[i][j];
        __syncthreads();

        // ---- O += P @ V (each thread: 4 rows x 8 cols) ----
#pragma unroll 2
        for (int jj = 0; jj < FKV; jj++) {
            float pv[4];
#pragma unroll
            for (int i = 0; i < 4; i++) pv[i] = sP[(ty * 4 + i) * PSTR + jj];
            float4 va = *(const float4*)&sV[jj * VSTR + tx * 8];
            float4 vb = *(const float4*)&sV[jj * VSTR + tx * 8 + 4];
            float vv[8] = {va.x, va.y, va.z, va.w, vb.x, vb.y, vb.z, vb.w};
#pragma unroll
            for (int i = 0; i < 4; i++)
#pragma unroll
                for (int j = 0; j < 8; j++)
                    o[i][j] += pv[i] * vv[j];
        }
    }

    // ---- finalize & write ----
#pragma unroll
    for (int i = 0; i < 4; i++) {
        float inv = 1.f / l[i];
        int r = qs + ty * 4 + i;
        float4 v0, v1;
        v0.x = o[i][0] * inv; v0.y = o[i][1] * inv;
        v0.z = o[i][2] * inv; v0.w = o[i][3] * inv;
        v1.x = o[i][4] * inv; v1.y = o[i][5] * inv;
        v1.z = o[i][6] * inv; v1.w = o[i][7] * inv;
        *(float4*)(O + base + (size_t)r * DIM + tx * 8)     = v0;
        *(float4*)(O + base + (size_t)r * DIM + tx * 8 + 4) = v1;
    }
}

// ---------------------------------------------------------------------------
// kernel_launch
// ---------------------------------------------------------------------------
extern "C" void kernel_launch(void* const* d_in, const int* in_sizes, int n_in,
                              void* d_out, int out_size)
{
    const float* x      = (const float*)d_in[0];
    // d_in[1] = causal mask (bool) — known tril, handled analytically
    const float* wq     = (const float*)d_in[2];
    const float* bq     = (const float*)d_in[3];
    const float* wk     = (const float*)d_in[4];
    const float* bk     = (const float*)d_in[5];
    const float* wv     = (const float*)d_in[6];
    const float* bv     = (const float*)d_in[7];
    const float* wo     = (const float*)d_in[8];
    const float* bo     = (const float*)d_in[9];
    const float* slopes = (const float*)d_in[10];
    float* out = (float*)d_out;

    float *dQ, *dK, *dV, *dO;
    cudaGetSymbolAddress((void**)&dQ, g_Q);
    cudaGetSymbolAddress((void**)&dK, g_K);
    cudaGetSymbolAddress((void**)&dV, g_V);
    cudaGetSymbolAddress((void**)&dO, g_O);

    const int smem_flash = (FQ * QSTR + FKV * KSTR + FKV * VSTR + FQ * PSTR) * (int)sizeof(float);
    cudaFuncSetAttribute(flash_attn_kernel,
                         cudaFuncAttributeMaxDynamicSharedMemorySize, smem_flash);

    dim3 gemmGrid(DIM / GBN, MROWS / GBM);   // (16, 32)
    dim3 gemmBlock(256);

    // QKV projections
    sgemm_bias_kernel<<<gemmGrid, gemmBlock>>>(x, wq, bq, dQ, MROWS, DIM, DIM);
    sgemm_bias_kernel<<<gemmGrid, gemmBlock>>>(x, wk, bk, dK, MROWS, DIM, DIM);
    sgemm_bias_kernel<<<gemmGrid, gemmBlock>>>(x, wv, bv, dV, MROWS, DIM, DIM);

    // Attention
    dim3 attnGrid(SEQ / FQ, HEADS, BATCH);   // (32, 16, 2)
    flash_attn_kernel<<<attnGrid, 256, smem_flash>>>(dQ, dK, dV, slopes, dO);

    // Output projection
    sgemm_bias_kernel<<<gemmGrid, gemmBlock>>>(dO, wo, bo, out, MROWS, DIM, DIM);
}